// round 2
// baseline (speedup 1.0000x reference)
#include <cuda_runtime.h>

// Problem constants
#define N_NODE 50000
#define N_EDGE 500000
#define RATES  2
#define VOCAB  4096
#define MS     128
#define OUTU   256
#define BAS    4

// ---------------- scratch (device globals; no allocation allowed) ----------
__device__ __align__(16) float g_W[RATES * VOCAB * MS];            // 4 MB
__device__ __align__(16) float g_M[RATES * 3 * VOCAB * OUTU];      // 25 MB
__device__ __align__(16) float g_p[2 * RATES * N_NODE * OUTU];     // 205 MB (side 0 = drug, side 1 = dis)
__device__ int g_cnt[2][N_NODE + 1];
__device__ int g_off[2][N_NODE + 1];
__device__ int g_cur[2][N_NODE];
__device__ int g_sorted[2][RATES * N_EDGE];                        // 8 MB

// ---------------- kernel 1: W[r] = att[r] @ basis ---------------------------
__global__ void __launch_bounds__(256) k_W(const float* __restrict__ att,
                                           const float* __restrict__ basis) {
    int idx = blockIdx.x * blockDim.x + threadIdx.x;
    if (idx >= RATES * VOCAB * MS) return;
    int r  = idx / (VOCAB * MS);
    int im = idx % (VOCAB * MS);
    float s = 0.f;
#pragma unroll
    for (int b = 0; b < BAS; b++)
        s += __ldg(&att[r * BAS + b]) * __ldg(&basis[b * (VOCAB * MS) + im]);
    g_W[idx] = s;
}

// ---------------- kernel 2: M[r][k] = W[r] @ fc_w[:,128k:128k+128]^T --------
// per (r,k): C[4096,256] = A[4096,128] * B[256,128]^T. 64x64 tile, 256 thr.
__global__ void __launch_bounds__(256) k_M(const float* __restrict__ fc_w) {
    int rk = blockIdx.z;
    int r = rk / 3, k = rk % 3;
    int i0 = blockIdx.x * 64;
    int o0 = blockIdx.y * 64;
    __shared__ float As[32][65];
    __shared__ float Bs[32][65];
    int tid = threadIdx.x;
    int tx = tid & 15, ty = tid >> 4;
    float acc[4][4];
#pragma unroll
    for (int u = 0; u < 4; u++)
#pragma unroll
        for (int v = 0; v < 4; v++) acc[u][v] = 0.f;

    const float* Wp = g_W + r * VOCAB * MS;
    for (int mc = 0; mc < MS; mc += 32) {
#pragma unroll
        for (int j = 0; j < 8; j++) {
            int f = j * 256 + tid;
            int ii = f >> 5, mm = f & 31;
            As[mm][ii] = Wp[(i0 + ii) * MS + mc + mm];
            Bs[mm][ii] = fc_w[(o0 + ii) * (3 * MS) + k * MS + mc + mm];
        }
        __syncthreads();
#pragma unroll
        for (int mm = 0; mm < 32; mm++) {
            float a[4], b[4];
#pragma unroll
            for (int u = 0; u < 4; u++) { a[u] = As[mm][ty * 4 + u]; b[u] = Bs[mm][tx * 4 + u]; }
#pragma unroll
            for (int u = 0; u < 4; u++)
#pragma unroll
                for (int v = 0; v < 4; v++) acc[u][v] += a[u] * b[v];
        }
        __syncthreads();
    }
    float* Mout = g_M + (size_t)((r * 3 + k) * VOCAB) * OUTU;
#pragma unroll
    for (int u = 0; u < 4; u++) {
        float4 o4 = make_float4(acc[u][0], acc[u][1], acc[u][2], acc[u][3]);
        *(float4*)(&Mout[(size_t)(i0 + ty * 4 + u) * OUTU + o0 + tx * 4]) = o4;
    }
}

// ---------------- kernel 3: p[side][r][n] = cj[n] * sum_k M[r][k][feat[n,k]]
// one warp per (side, r, node); 2 float4 per lane = 256 floats
__global__ void __launch_bounds__(256) k_p(const int* __restrict__ drug_feat,
                                           const int* __restrict__ dis_feat,
                                           const float* __restrict__ cj_drug,
                                           const float* __restrict__ cj_dis) {
    int gw = (blockIdx.x * blockDim.x + threadIdx.x) >> 5;
    int lane = threadIdx.x & 31;
    if (gw >= 2 * RATES * N_NODE) return;
    int side = gw / (RATES * N_NODE);
    int rem  = gw % (RATES * N_NODE);
    int r = rem / N_NODE, n = rem % N_NODE;

    const int* feat = side ? dis_feat : drug_feat;
    float cj = side ? __ldg(&cj_dis[n]) : __ldg(&cj_drug[n]);
    int f0 = __ldg(&feat[n * 3 + 0]);
    int f1 = __ldg(&feat[n * 3 + 1]);
    int f2 = __ldg(&feat[n * 3 + 2]);

    const float4* m0 = (const float4*)(g_M + (size_t)((r * 3 + 0) * VOCAB + f0) * OUTU);
    const float4* m1 = (const float4*)(g_M + (size_t)((r * 3 + 1) * VOCAB + f1) * OUTU);
    const float4* m2 = (const float4*)(g_M + (size_t)((r * 3 + 2) * VOCAB + f2) * OUTU);
    float4* out = (float4*)(g_p + (size_t)((side * RATES + r) * N_NODE + n) * OUTU);

#pragma unroll
    for (int j = 0; j < 2; j++) {
        int c = lane + j * 32;
        float4 a = m0[c], b = m1[c], d = m2[c];
        float4 o;
        o.x = cj * (a.x + b.x + d.x);
        o.y = cj * (a.y + b.y + d.y);
        o.z = cj * (a.z + b.z + d.z);
        o.w = cj * (a.w + b.w + d.w);
        out[c] = o;
    }
}

// ---------------- kernel 4: zero histograms --------------------------------
__global__ void __launch_bounds__(256) k_zero() {
    int i = blockIdx.x * blockDim.x + threadIdx.x;
    if (i < 2 * (N_NODE + 1)) ((int*)g_cnt)[i] = 0;
}

// ---------------- kernel 5: per-destination edge histogram -----------------
__global__ void __launch_bounds__(256) k_count(const int* __restrict__ edge_src,
                                               const int* __restrict__ edge_dst) {
    for (int idx = blockIdx.x * blockDim.x + threadIdx.x; idx < RATES * N_EDGE;
         idx += gridDim.x * blockDim.x) {
        int s = __ldg(&edge_src[idx]);
        int d = __ldg(&edge_dst[idx]);
        atomicAdd(&g_cnt[0][s], 1);   // dir 0: drug_out CSR keyed by src
        atomicAdd(&g_cnt[1][d], 1);   // dir 1: dis_out  CSR keyed by dst
    }
}

// ---------------- kernel 6: exclusive scan -> offsets (one block per dir) ---
__global__ void __launch_bounds__(1024) k_scan() {
    const int T = 1024;
    int dir = blockIdx.x;
    int t = threadIdx.x;
    __shared__ int ssum[T];
    const int chunk = (N_NODE + T - 1) / T;
    int begin = t * chunk;
    int end = begin + chunk; if (end > N_NODE) end = N_NODE;
    int s = 0;
    for (int i = begin; i < end && begin < N_NODE; i++) s += g_cnt[dir][i];
    ssum[t] = s;
    __syncthreads();
    // Hillis-Steele inclusive scan
    for (int ofs = 1; ofs < T; ofs <<= 1) {
        int v = (t >= ofs) ? ssum[t - ofs] : 0;
        __syncthreads();
        ssum[t] += v;
        __syncthreads();
    }
    int run = ssum[t] - s;  // exclusive base for this thread
    for (int i = begin; i < end && begin < N_NODE; i++) {
        int c = g_cnt[dir][i];
        g_off[dir][i] = run;
        g_cur[dir][i] = run;
        run += c;
    }
    if (t == T - 1) g_off[dir][N_NODE] = ssum[T - 1];
}

// ---------------- kernel 7: scatter edge -> sorted gather index ------------
__global__ void __launch_bounds__(256) k_scatter(const int* __restrict__ edge_src,
                                                 const int* __restrict__ edge_dst) {
    for (int idx = blockIdx.x * blockDim.x + threadIdx.x; idx < RATES * N_EDGE;
         idx += gridDim.x * blockDim.x) {
        int r = idx / N_EDGE;
        int s = __ldg(&edge_src[idx]);
        int d = __ldg(&edge_dst[idx]);
        int p0 = atomicAdd(&g_cur[0][s], 1);
        g_sorted[0][p0] = r * N_NODE + d;   // drug_out pulls p_dis rows
        int p1 = atomicAdd(&g_cur[1][d], 1);
        g_sorted[1][p1] = r * N_NODE + s;   // dis_out pulls p_drug rows
    }
}

// ---------------- kernel 8: pull aggregation + scale + bias ----------------
// 64 threads per node (one float4 each), 4 nodes/block, grid.y = direction
__global__ void __launch_bounds__(256) k_agg(const float* __restrict__ ci_drug,
                                             const float* __restrict__ ci_dis,
                                             const float* __restrict__ fc_b,
                                             float* __restrict__ out) {
    int dir = blockIdx.y;
    int node = blockIdx.x * 4 + (threadIdx.x >> 6);
    int t = threadIdx.x & 63;
    if (node >= N_NODE) return;

    int start = g_off[dir][node];
    int end   = g_off[dir][node + 1];
    // dir 0 (drug_out) gathers p side 1 (dis); dir 1 (dis_out) gathers side 0
    const float4* pbase = (const float4*)(g_p + (dir == 0 ? (size_t)RATES * N_NODE * OUTU : 0));
    const int* srt = g_sorted[dir];

    float4 acc0 = make_float4(0.f, 0.f, 0.f, 0.f);
    float4 acc1 = make_float4(0.f, 0.f, 0.f, 0.f);
    int e = start;
    // 2-deep unroll: two independent gathers in flight per lane
    for (; e + 1 < end; e += 2) {
        int gi0 = __ldg(&srt[e]);
        int gi1 = __ldg(&srt[e + 1]);
        float4 v0 = pbase[(size_t)gi0 * (OUTU / 4) + t];
        float4 v1 = pbase[(size_t)gi1 * (OUTU / 4) + t];
        acc0.x += v0.x; acc0.y += v0.y; acc0.z += v0.z; acc0.w += v0.w;
        acc1.x += v1.x; acc1.y += v1.y; acc1.z += v1.z; acc1.w += v1.w;
    }
    if (e < end) {
        int gi = __ldg(&srt[e]);
        float4 v = pbase[(size_t)gi * (OUTU / 4) + t];
        acc0.x += v.x; acc0.y += v.y; acc0.z += v.z; acc0.w += v.w;
    }
    acc0.x += acc1.x; acc0.y += acc1.y; acc0.z += acc1.z; acc0.w += acc1.w;

    float ci = (dir == 0) ? __ldg(&ci_drug[node]) : __ldg(&ci_dis[node]);
    float4 b = ((const float4*)fc_b)[t];
    float4 o;
    o.x = ci * acc0.x + b.x;
    o.y = ci * acc0.y + b.y;
    o.z = ci * acc0.z + b.z;
    o.w = ci * acc0.w + b.w;
    size_t row = (dir == 0) ? (size_t)node : (size_t)(N_NODE + node);
    ((float4*)out)[row * (OUTU / 4) + t] = o;
}

// ---------------- launch ---------------------------------------------------
extern "C" void kernel_launch(void* const* d_in, const int* in_sizes, int n_in,
                              void* d_out, int out_size) {
    const int*   drug_feat = (const int*)d_in[0];
    const int*   dis_feat  = (const int*)d_in[1];
    const int*   edge_src  = (const int*)d_in[2];
    const int*   edge_dst  = (const int*)d_in[3];
    const float* cj_drug   = (const float*)d_in[4];
    const float* ci_drug   = (const float*)d_in[5];
    const float* cj_dis    = (const float*)d_in[6];
    const float* ci_dis    = (const float*)d_in[7];
    const float* att       = (const float*)d_in[8];
    const float* basis     = (const float*)d_in[9];
    const float* fc_w      = (const float*)d_in[10];
    const float* fc_b      = (const float*)d_in[11];
    float* out = (float*)d_out;

    // 1. W = att @ basis
    k_W<<<(RATES * VOCAB * MS + 255) / 256, 256>>>(att, basis);

    // 2. M[r][k] = W[r] @ fc_w_k^T
    dim3 gM(VOCAB / 64, OUTU / 64, RATES * 3);
    k_M<<<gM, 256>>>(fc_w);

    // 3. node messages p (both sides, both ratings)
    int warps = 2 * RATES * N_NODE;
    k_p<<<(warps + 7) / 8, 256>>>(drug_feat, dis_feat, cj_drug, cj_dis);

    // 4-7. counting sort -> CSR
    k_zero<<<(2 * (N_NODE + 1) + 255) / 256, 256>>>();
    k_count<<<1184, 256>>>(edge_src, edge_dst);
    k_scan<<<2, 1024>>>();
    k_scatter<<<1184, 256>>>(edge_src, edge_dst);

    // 8. pull aggregation + epilogue
    dim3 ga((N_NODE + 3) / 4, 2);
    k_agg<<<ga, 256>>>(ci_drug, ci_dis, fc_b, out);
}

// round 3
// speedup vs baseline: 1.2973x; 1.2973x over previous
#include <cuda_runtime.h>
#include <cuda_fp16.h>

// Problem constants
#define N_NODE 50000
#define N_EDGE 500000
#define RATES  2
#define VOCAB  4096
#define MS     128
#define OUTU   256
#define BAS    4

// ---------------- scratch (device globals; no allocation allowed) ----------
__device__ __align__(16) float  g_W[RATES * VOCAB * MS];             // 4 MB fp32
__device__ __align__(16) __half g_Mh[RATES * 3 * VOCAB * OUTU];      // 12.5 MB fp16
__device__ __align__(16) __half g_ph[2 * RATES * N_NODE * OUTU];     // 102 MB fp16
__device__ int g_cnt[2][N_NODE + 1];
__device__ int g_off[2][N_NODE + 1];
__device__ int g_cur[2][N_NODE];
__device__ int g_sorted[2][RATES * N_EDGE];                          // 8 MB

// ---------------- kernel 1: W[r] = att[r] @ basis ---------------------------
__global__ void __launch_bounds__(256) k_W(const float* __restrict__ att,
                                           const float* __restrict__ basis) {
    int idx = blockIdx.x * blockDim.x + threadIdx.x;
    if (idx >= RATES * VOCAB * MS) return;
    int r  = idx / (VOCAB * MS);
    int im = idx % (VOCAB * MS);
    float s = 0.f;
#pragma unroll
    for (int b = 0; b < BAS; b++)
        s += __ldg(&att[r * BAS + b]) * __ldg(&basis[b * (VOCAB * MS) + im]);
    g_W[idx] = s;
}

// ---------------- kernel 2: M[r][k] = W[r] @ fc_w[:,128k:+128]^T (fp16 out) -
__global__ void __launch_bounds__(256) k_M(const float* __restrict__ fc_w) {
    int rk = blockIdx.z;
    int r = rk / 3, k = rk % 3;
    int i0 = blockIdx.x * 64;
    int o0 = blockIdx.y * 64;
    __shared__ float As[32][65];
    __shared__ float Bs[32][65];
    int tid = threadIdx.x;
    int tx = tid & 15, ty = tid >> 4;
    float acc[4][4];
#pragma unroll
    for (int u = 0; u < 4; u++)
#pragma unroll
        for (int v = 0; v < 4; v++) acc[u][v] = 0.f;

    const float* Wp = g_W + r * VOCAB * MS;
    for (int mc = 0; mc < MS; mc += 32) {
#pragma unroll
        for (int j = 0; j < 8; j++) {
            int f = j * 256 + tid;
            int ii = f >> 5, mm = f & 31;
            As[mm][ii] = Wp[(i0 + ii) * MS + mc + mm];
            Bs[mm][ii] = fc_w[(o0 + ii) * (3 * MS) + k * MS + mc + mm];
        }
        __syncthreads();
#pragma unroll
        for (int mm = 0; mm < 32; mm++) {
            float a[4], b[4];
#pragma unroll
            for (int u = 0; u < 4; u++) { a[u] = As[mm][ty * 4 + u]; b[u] = Bs[mm][tx * 4 + u]; }
#pragma unroll
            for (int u = 0; u < 4; u++)
#pragma unroll
                for (int v = 0; v < 4; v++) acc[u][v] += a[u] * b[v];
        }
        __syncthreads();
    }
    __half* Mout = g_Mh + (size_t)((r * 3 + k) * VOCAB) * OUTU;
#pragma unroll
    for (int u = 0; u < 4; u++) {
        __half2 h0 = __floats2half2_rn(acc[u][0], acc[u][1]);
        __half2 h1 = __floats2half2_rn(acc[u][2], acc[u][3]);
        uint2 pk;
        pk.x = *(unsigned int*)&h0;
        pk.y = *(unsigned int*)&h1;
        *(uint2*)(&Mout[(size_t)(i0 + ty * 4 + u) * OUTU + o0 + tx * 4]) = pk;
    }
}

// ---------------- kernel 3: p[side][r][n] = cj[n]*sum_k M[r][k][feat[n,k]] --
// one warp per (side, r, node); each lane owns 8 halves (one uint4 = 16B)
__global__ void __launch_bounds__(256) k_p(const int* __restrict__ drug_feat,
                                           const int* __restrict__ dis_feat,
                                           const float* __restrict__ cj_drug,
                                           const float* __restrict__ cj_dis) {
    int gw = (blockIdx.x * blockDim.x + threadIdx.x) >> 5;
    int lane = threadIdx.x & 31;
    if (gw >= 2 * RATES * N_NODE) return;
    int side = gw / (RATES * N_NODE);
    int rem  = gw % (RATES * N_NODE);
    int r = rem / N_NODE, n = rem % N_NODE;

    const int* feat = side ? dis_feat : drug_feat;
    float cj = side ? __ldg(&cj_dis[n]) : __ldg(&cj_drug[n]);
    int f0 = __ldg(&feat[n * 3 + 0]);
    int f1 = __ldg(&feat[n * 3 + 1]);
    int f2 = __ldg(&feat[n * 3 + 2]);

    const uint4* m0 = (const uint4*)(g_Mh + (size_t)((r * 3 + 0) * VOCAB + f0) * OUTU);
    const uint4* m1 = (const uint4*)(g_Mh + (size_t)((r * 3 + 1) * VOCAB + f1) * OUTU);
    const uint4* m2 = (const uint4*)(g_Mh + (size_t)((r * 3 + 2) * VOCAB + f2) * OUTU);
    uint4* out = (uint4*)(g_ph + (size_t)((side * RATES + r) * N_NODE + n) * OUTU);

    uint4 a = m0[lane], b = m1[lane], c = m2[lane];
    const unsigned int* au = (const unsigned int*)&a;
    const unsigned int* bu = (const unsigned int*)&b;
    const unsigned int* cu = (const unsigned int*)&c;
    uint4 o;
    unsigned int* ou = (unsigned int*)&o;
#pragma unroll
    for (int j = 0; j < 4; j++) {
        float2 fa = __half22float2(*(const __half2*)&au[j]);
        float2 fb = __half22float2(*(const __half2*)&bu[j]);
        float2 fc = __half22float2(*(const __half2*)&cu[j]);
        float2 s;
        s.x = cj * (fa.x + fb.x + fc.x);
        s.y = cj * (fa.y + fb.y + fc.y);
        __half2 h = __floats2half2_rn(s.x, s.y);
        ou[j] = *(unsigned int*)&h;
    }
    out[lane] = o;
}

// ---------------- kernel 4: zero histograms --------------------------------
__global__ void __launch_bounds__(256) k_zero() {
    int i = blockIdx.x * blockDim.x + threadIdx.x;
    if (i < 2 * (N_NODE + 1)) ((int*)g_cnt)[i] = 0;
}

// ---------------- kernel 5: per-destination edge histogram -----------------
__global__ void __launch_bounds__(256) k_count(const int* __restrict__ edge_src,
                                               const int* __restrict__ edge_dst) {
    for (int idx = blockIdx.x * blockDim.x + threadIdx.x; idx < RATES * N_EDGE;
         idx += gridDim.x * blockDim.x) {
        int s = __ldg(&edge_src[idx]);
        int d = __ldg(&edge_dst[idx]);
        atomicAdd(&g_cnt[0][s], 1);   // dir 0: drug_out CSR keyed by src
        atomicAdd(&g_cnt[1][d], 1);   // dir 1: dis_out  CSR keyed by dst
    }
}

// ---------------- kernel 6: exclusive scan -> offsets (one block per dir) ---
__global__ void __launch_bounds__(1024) k_scan() {
    const int T = 1024;
    int dir = blockIdx.x;
    int t = threadIdx.x;
    __shared__ int ssum[T];
    const int chunk = (N_NODE + T - 1) / T;
    int begin = t * chunk;
    int end = begin + chunk; if (end > N_NODE) end = N_NODE;
    int s = 0;
    for (int i = begin; i < end && begin < N_NODE; i++) s += g_cnt[dir][i];
    ssum[t] = s;
    __syncthreads();
    for (int ofs = 1; ofs < T; ofs <<= 1) {
        int v = (t >= ofs) ? ssum[t - ofs] : 0;
        __syncthreads();
        ssum[t] += v;
        __syncthreads();
    }
    int run = ssum[t] - s;
    for (int i = begin; i < end && begin < N_NODE; i++) {
        int c = g_cnt[dir][i];
        g_off[dir][i] = run;
        g_cur[dir][i] = run;
        run += c;
    }
    if (t == T - 1) g_off[dir][N_NODE] = ssum[T - 1];
}

// ---------------- kernel 7: scatter edge -> sorted gather index ------------
__global__ void __launch_bounds__(256) k_scatter(const int* __restrict__ edge_src,
                                                 const int* __restrict__ edge_dst) {
    for (int idx = blockIdx.x * blockDim.x + threadIdx.x; idx < RATES * N_EDGE;
         idx += gridDim.x * blockDim.x) {
        int r = idx / N_EDGE;
        int s = __ldg(&edge_src[idx]);
        int d = __ldg(&edge_dst[idx]);
        int p0 = atomicAdd(&g_cur[0][s], 1);
        g_sorted[0][p0] = r * N_NODE + d;   // drug_out pulls p_dis rows
        int p1 = atomicAdd(&g_cur[1][d], 1);
        g_sorted[1][p1] = r * N_NODE + s;   // dis_out pulls p_drug rows
    }
}

// ---------------- kernel 8: pull aggregation + scale + bias (one dir) ------
// one warp per node; lane owns 8 output cols (one uint4 of fp16 per row read)
__global__ void __launch_bounds__(256) k_agg(int dir,
                                             const float* __restrict__ ci_drug,
                                             const float* __restrict__ ci_dis,
                                             const float* __restrict__ fc_b,
                                             float* __restrict__ out) {
    int node = blockIdx.x * 8 + (threadIdx.x >> 5);
    int lane = threadIdx.x & 31;
    if (node >= N_NODE) return;

    int start = g_off[dir][node];
    int end   = g_off[dir][node + 1];
    // dir 0 (drug_out) gathers p side 1 (dis); dir 1 (dis_out) gathers side 0
    const uint4* pbase = (const uint4*)(g_ph + (dir == 0 ? (size_t)RATES * N_NODE * OUTU : 0));
    const int* srt = g_sorted[dir];

    float acc[8];
#pragma unroll
    for (int j = 0; j < 8; j++) acc[j] = 0.f;

    int e = start;
    for (; e + 1 < end; e += 2) {
        int gi0 = __ldg(&srt[e]);
        int gi1 = __ldg(&srt[e + 1]);
        uint4 v0 = pbase[(size_t)gi0 * 32 + lane];
        uint4 v1 = pbase[(size_t)gi1 * 32 + lane];
        const unsigned int* u0 = (const unsigned int*)&v0;
        const unsigned int* u1 = (const unsigned int*)&v1;
#pragma unroll
        for (int j = 0; j < 4; j++) {
            float2 f0 = __half22float2(*(const __half2*)&u0[j]);
            float2 f1 = __half22float2(*(const __half2*)&u1[j]);
            acc[2 * j]     += f0.x + f1.x;
            acc[2 * j + 1] += f0.y + f1.y;
        }
    }
    if (e < end) {
        int gi = __ldg(&srt[e]);
        uint4 v = pbase[(size_t)gi * 32 + lane];
        const unsigned int* u = (const unsigned int*)&v;
#pragma unroll
        for (int j = 0; j < 4; j++) {
            float2 f = __half22float2(*(const __half2*)&u[j]);
            acc[2 * j]     += f.x;
            acc[2 * j + 1] += f.y;
        }
    }

    float ci = (dir == 0) ? __ldg(&ci_drug[node]) : __ldg(&ci_dis[node]);
    float4 b0 = ((const float4*)fc_b)[lane * 2];
    float4 b1 = ((const float4*)fc_b)[lane * 2 + 1];
    float4 o0, o1;
    o0.x = ci * acc[0] + b0.x;  o0.y = ci * acc[1] + b0.y;
    o0.z = ci * acc[2] + b0.z;  o0.w = ci * acc[3] + b0.w;
    o1.x = ci * acc[4] + b1.x;  o1.y = ci * acc[5] + b1.y;
    o1.z = ci * acc[6] + b1.z;  o1.w = ci * acc[7] + b1.w;
    size_t row = (dir == 0) ? (size_t)node : (size_t)(N_NODE + node);
    float4* orow = (float4*)out + row * (OUTU / 4);
    orow[lane * 2]     = o0;
    orow[lane * 2 + 1] = o1;
}

// ---------------- launch ---------------------------------------------------
extern "C" void kernel_launch(void* const* d_in, const int* in_sizes, int n_in,
                              void* d_out, int out_size) {
    const int*   drug_feat = (const int*)d_in[0];
    const int*   dis_feat  = (const int*)d_in[1];
    const int*   edge_src  = (const int*)d_in[2];
    const int*   edge_dst  = (const int*)d_in[3];
    const float* cj_drug   = (const float*)d_in[4];
    const float* ci_drug   = (const float*)d_in[5];
    const float* cj_dis    = (const float*)d_in[6];
    const float* ci_dis    = (const float*)d_in[7];
    const float* att       = (const float*)d_in[8];
    const float* basis     = (const float*)d_in[9];
    const float* fc_w      = (const float*)d_in[10];
    const float* fc_b      = (const float*)d_in[11];
    float* out = (float*)d_out;

    // 1. W = att @ basis
    k_W<<<(RATES * VOCAB * MS + 255) / 256, 256>>>(att, basis);

    // 2. M[r][k] = W[r] @ fc_w_k^T  (fp16 output)
    dim3 gM(VOCAB / 64, OUTU / 64, RATES * 3);
    k_M<<<gM, 256>>>(fc_w);

    // 3. node messages p (both sides, both ratings) -> fp16
    int warps = 2 * RATES * N_NODE;
    k_p<<<(warps + 7) / 8, 256>>>(drug_feat, dis_feat, cj_drug, cj_dis);

    // 4-7. counting sort -> CSR
    k_zero<<<(2 * (N_NODE + 1) + 255) / 256, 256>>>();
    k_count<<<1184, 256>>>(edge_src, edge_dst);
    k_scan<<<2, 1024>>>();
    k_scatter<<<1184, 256>>>(edge_src, edge_dst);

    // 8. pull aggregation, one direction at a time (keep 51 MB table L2-resident)
    int ablocks = (N_NODE + 7) / 8;
    k_agg<<<ablocks, 256>>>(0, ci_drug, ci_dis, fc_b, out);
    k_agg<<<ablocks, 256>>>(1, ci_drug, ci_dis, fc_b, out);
}

// round 4
// speedup vs baseline: 1.6724x; 1.2891x over previous
#include <cuda_runtime.h>
#include <cuda_fp16.h>

// Problem constants
#define N_NODE 50000
#define N_EDGE 500000
#define RATES  2
#define VOCAB  4096
#define MS     128
#define OUTU   256
#define BAS    4

// ---------------- scratch (device globals; no allocation allowed) ----------
__device__ __align__(16) float  g_W[RATES * VOCAB * MS];             // 4 MB fp32
__device__ __align__(16) __half g_Mh[RATES * 3 * VOCAB * OUTU];      // 12.5 MB fp16
__device__ __align__(16) __half g_ph[2 * RATES * N_NODE * OUTU];     // 102 MB fp16
__device__ int g_cnt[2][N_NODE + 1];
__device__ int g_off[2][N_NODE + 1];
__device__ int g_cur[2][N_NODE];
__device__ int g_sorted[2][RATES * N_EDGE];                          // 8 MB

// ---------------- kernel 1: W[r] = att[r] @ basis ---------------------------
__global__ void __launch_bounds__(256) k_W(const float* __restrict__ att,
                                           const float* __restrict__ basis) {
    int idx = blockIdx.x * blockDim.x + threadIdx.x;
    if (idx >= RATES * VOCAB * MS) return;
    int r  = idx / (VOCAB * MS);
    int im = idx % (VOCAB * MS);
    float s = 0.f;
#pragma unroll
    for (int b = 0; b < BAS; b++)
        s += __ldg(&att[r * BAS + b]) * __ldg(&basis[b * (VOCAB * MS) + im]);
    g_W[idx] = s;
}

// ---------------- kernel 2: M[r][k] = W[r] @ fc_w[:,128k:+128]^T (fp16 out) -
__global__ void __launch_bounds__(256) k_M(const float* __restrict__ fc_w) {
    int rk = blockIdx.z;
    int r = rk / 3, k = rk % 3;
    int i0 = blockIdx.x * 64;
    int o0 = blockIdx.y * 64;
    __shared__ float As[32][65];
    __shared__ float Bs[32][65];
    int tid = threadIdx.x;
    int tx = tid & 15, ty = tid >> 4;
    float acc[4][4];
#pragma unroll
    for (int u = 0; u < 4; u++)
#pragma unroll
        for (int v = 0; v < 4; v++) acc[u][v] = 0.f;

    const float* Wp = g_W + r * VOCAB * MS;
    for (int mc = 0; mc < MS; mc += 32) {
#pragma unroll
        for (int j = 0; j < 8; j++) {
            int f = j * 256 + tid;
            int ii = f >> 5, mm = f & 31;
            As[mm][ii] = Wp[(i0 + ii) * MS + mc + mm];
            Bs[mm][ii] = fc_w[(o0 + ii) * (3 * MS) + k * MS + mc + mm];
        }
        __syncthreads();
#pragma unroll
        for (int mm = 0; mm < 32; mm++) {
            float a[4], b[4];
#pragma unroll
            for (int u = 0; u < 4; u++) { a[u] = As[mm][ty * 4 + u]; b[u] = Bs[mm][tx * 4 + u]; }
#pragma unroll
            for (int u = 0; u < 4; u++)
#pragma unroll
                for (int v = 0; v < 4; v++) acc[u][v] += a[u] * b[v];
        }
        __syncthreads();
    }
    __half* Mout = g_Mh + (size_t)((r * 3 + k) * VOCAB) * OUTU;
#pragma unroll
    for (int u = 0; u < 4; u++) {
        __half2 h0 = __floats2half2_rn(acc[u][0], acc[u][1]);
        __half2 h1 = __floats2half2_rn(acc[u][2], acc[u][3]);
        uint2 pk;
        pk.x = *(unsigned int*)&h0;
        pk.y = *(unsigned int*)&h1;
        *(uint2*)(&Mout[(size_t)(i0 + ty * 4 + u) * OUTU + o0 + tx * 4]) = pk;
    }
}

// ---------------- kernel 3: p[side][r][n] = cj[n]*sum_k M[r][k][feat[n,k]] --
// one warp per (side, r, node); each lane owns 8 halves (one uint4 = 16B)
__global__ void __launch_bounds__(256) k_p(const int* __restrict__ drug_feat,
                                           const int* __restrict__ dis_feat,
                                           const float* __restrict__ cj_drug,
                                           const float* __restrict__ cj_dis) {
    int gw = (blockIdx.x * blockDim.x + threadIdx.x) >> 5;
    int lane = threadIdx.x & 31;
    if (gw >= 2 * RATES * N_NODE) return;
    int side = gw / (RATES * N_NODE);
    int rem  = gw % (RATES * N_NODE);
    int r = rem / N_NODE, n = rem % N_NODE;

    const int* feat = side ? dis_feat : drug_feat;
    float cj = side ? __ldg(&cj_dis[n]) : __ldg(&cj_drug[n]);
    int f0 = __ldg(&feat[n * 3 + 0]);
    int f1 = __ldg(&feat[n * 3 + 1]);
    int f2 = __ldg(&feat[n * 3 + 2]);

    const uint4* m0 = (const uint4*)(g_Mh + (size_t)((r * 3 + 0) * VOCAB + f0) * OUTU);
    const uint4* m1 = (const uint4*)(g_Mh + (size_t)((r * 3 + 1) * VOCAB + f1) * OUTU);
    const uint4* m2 = (const uint4*)(g_Mh + (size_t)((r * 3 + 2) * VOCAB + f2) * OUTU);
    uint4* out = (uint4*)(g_ph + (size_t)((side * RATES + r) * N_NODE + n) * OUTU);

    uint4 a = m0[lane], b = m1[lane], c = m2[lane];
    const unsigned int* au = (const unsigned int*)&a;
    const unsigned int* bu = (const unsigned int*)&b;
    const unsigned int* cu = (const unsigned int*)&c;
    uint4 o;
    unsigned int* ou = (unsigned int*)&o;
#pragma unroll
    for (int j = 0; j < 4; j++) {
        float2 fa = __half22float2(*(const __half2*)&au[j]);
        float2 fb = __half22float2(*(const __half2*)&bu[j]);
        float2 fc = __half22float2(*(const __half2*)&cu[j]);
        float2 s;
        s.x = cj * (fa.x + fb.x + fc.x);
        s.y = cj * (fa.y + fb.y + fc.y);
        __half2 h = __floats2half2_rn(s.x, s.y);
        ou[j] = *(unsigned int*)&h;
    }
    out[lane] = o;
}

// ---------------- kernel 4: zero histograms --------------------------------
__global__ void __launch_bounds__(256) k_zero() {
    int i = blockIdx.x * blockDim.x + threadIdx.x;
    if (i < 2 * (N_NODE + 1)) ((int*)g_cnt)[i] = 0;
}

// ---------------- kernel 5: per-destination edge histogram -----------------
__global__ void __launch_bounds__(256) k_count(const int* __restrict__ edge_src,
                                               const int* __restrict__ edge_dst) {
    for (int idx = blockIdx.x * blockDim.x + threadIdx.x; idx < RATES * N_EDGE;
         idx += gridDim.x * blockDim.x) {
        int s = __ldg(&edge_src[idx]);
        int d = __ldg(&edge_dst[idx]);
        atomicAdd(&g_cnt[0][s], 1);   // dir 0: drug_out CSR keyed by src
        atomicAdd(&g_cnt[1][d], 1);   // dir 1: dis_out  CSR keyed by dst
    }
}

// ---------------- kernel 6: exclusive scan -> offsets (one block per dir) ---
__global__ void __launch_bounds__(1024) k_scan() {
    const int T = 1024;
    int dir = blockIdx.x;
    int t = threadIdx.x;
    __shared__ int ssum[T];
    const int chunk = (N_NODE + T - 1) / T;
    int begin = t * chunk;
    int end = begin + chunk; if (end > N_NODE) end = N_NODE;
    int s = 0;
    for (int i = begin; i < end && begin < N_NODE; i++) s += g_cnt[dir][i];
    ssum[t] = s;
    __syncthreads();
    for (int ofs = 1; ofs < T; ofs <<= 1) {
        int v = (t >= ofs) ? ssum[t - ofs] : 0;
        __syncthreads();
        ssum[t] += v;
        __syncthreads();
    }
    int run = ssum[t] - s;
    for (int i = begin; i < end && begin < N_NODE; i++) {
        int c = g_cnt[dir][i];
        g_off[dir][i] = run;
        g_cur[dir][i] = run;
        run += c;
    }
    if (t == T - 1) g_off[dir][N_NODE] = ssum[T - 1];
}

// ---------------- kernel 7: scatter edge -> sorted gather index ------------
__global__ void __launch_bounds__(256) k_scatter(const int* __restrict__ edge_src,
                                                 const int* __restrict__ edge_dst) {
    for (int idx = blockIdx.x * blockDim.x + threadIdx.x; idx < RATES * N_EDGE;
         idx += gridDim.x * blockDim.x) {
        int r = idx / N_EDGE;
        int s = __ldg(&edge_src[idx]);
        int d = __ldg(&edge_dst[idx]);
        int p0 = atomicAdd(&g_cur[0][s], 1);
        g_sorted[0][p0] = r * N_NODE + d;   // drug_out pulls p_dis rows
        int p1 = atomicAdd(&g_cur[1][d], 1);
        g_sorted[1][p1] = r * N_NODE + s;   // dis_out pulls p_drug rows
    }
}

// ---------------- kernel 8: pull aggregation + scale + bias (one dir) ------
// one warp per node; lane owns 8 output cols; 4-deep MLP unroll
__global__ void __launch_bounds__(256) k_agg(int dir,
                                             const float* __restrict__ ci_drug,
                                             const float* __restrict__ ci_dis,
                                             const float* __restrict__ fc_b,
                                             float* __restrict__ out) {
    int node = blockIdx.x * 8 + (threadIdx.x >> 5);
    int lane = threadIdx.x & 31;
    if (node >= N_NODE) return;

    int start = g_off[dir][node];
    int end   = g_off[dir][node + 1];
    // dir 0 (drug_out) gathers p side 1 (dis); dir 1 (dis_out) gathers side 0
    const uint4* pbase = (const uint4*)(g_ph + (dir == 0 ? (size_t)RATES * N_NODE * OUTU : 0));
    const int* srt = g_sorted[dir];

    float acc[8];
#pragma unroll
    for (int j = 0; j < 8; j++) acc[j] = 0.f;

    int e = start;
    for (; e + 3 < end; e += 4) {
        int gi0 = __ldg(&srt[e]);
        int gi1 = __ldg(&srt[e + 1]);
        int gi2 = __ldg(&srt[e + 2]);
        int gi3 = __ldg(&srt[e + 3]);
        uint4 v0 = pbase[(size_t)gi0 * 32 + lane];
        uint4 v1 = pbase[(size_t)gi1 * 32 + lane];
        uint4 v2 = pbase[(size_t)gi2 * 32 + lane];
        uint4 v3 = pbase[(size_t)gi3 * 32 + lane];
        const unsigned int* u0 = (const unsigned int*)&v0;
        const unsigned int* u1 = (const unsigned int*)&v1;
        const unsigned int* u2 = (const unsigned int*)&v2;
        const unsigned int* u3 = (const unsigned int*)&v3;
#pragma unroll
        for (int j = 0; j < 4; j++) {
            float2 f0 = __half22float2(*(const __half2*)&u0[j]);
            float2 f1 = __half22float2(*(const __half2*)&u1[j]);
            float2 f2 = __half22float2(*(const __half2*)&u2[j]);
            float2 f3 = __half22float2(*(const __half2*)&u3[j]);
            acc[2 * j]     += (f0.x + f1.x) + (f2.x + f3.x);
            acc[2 * j + 1] += (f0.y + f1.y) + (f2.y + f3.y);
        }
    }
    for (; e < end; e++) {
        int gi = __ldg(&srt[e]);
        uint4 v = pbase[(size_t)gi * 32 + lane];
        const unsigned int* u = (const unsigned int*)&v;
#pragma unroll
        for (int j = 0; j < 4; j++) {
            float2 f = __half22float2(*(const __half2*)&u[j]);
            acc[2 * j]     += f.x;
            acc[2 * j + 1] += f.y;
        }
    }

    float ci = (dir == 0) ? __ldg(&ci_drug[node]) : __ldg(&ci_dis[node]);
    float4 b0 = ((const float4*)fc_b)[lane * 2];
    float4 b1 = ((const float4*)fc_b)[lane * 2 + 1];
    float4 o0, o1;
    o0.x = ci * acc[0] + b0.x;  o0.y = ci * acc[1] + b0.y;
    o0.z = ci * acc[2] + b0.z;  o0.w = ci * acc[3] + b0.w;
    o1.x = ci * acc[4] + b1.x;  o1.y = ci * acc[5] + b1.y;
    o1.z = ci * acc[6] + b1.z;  o1.w = ci * acc[7] + b1.w;
    size_t row = (dir == 0) ? (size_t)node : (size_t)(N_NODE + node);
    float4* orow = (float4*)out + row * (OUTU / 4);
    orow[lane * 2]     = o0;
    orow[lane * 2 + 1] = o1;
}

// ---------------- launch ---------------------------------------------------
extern "C" void kernel_launch(void* const* d_in, const int* in_sizes, int n_in,
                              void* d_out, int out_size) {
    const int*   drug_feat = (const int*)d_in[0];
    const int*   dis_feat  = (const int*)d_in[1];
    const int*   edge_src  = (const int*)d_in[2];
    const int*   edge_dst  = (const int*)d_in[3];
    const float* cj_drug   = (const float*)d_in[4];
    const float* ci_drug   = (const float*)d_in[5];
    const float* cj_dis    = (const float*)d_in[6];
    const float* ci_dis    = (const float*)d_in[7];
    const float* att       = (const float*)d_in[8];
    const float* basis     = (const float*)d_in[9];
    const float* fc_w      = (const float*)d_in[10];
    const float* fc_b      = (const float*)d_in[11];
    float* out = (float*)d_out;

    // Fork a side stream for the CSR build; it is independent of the W/M/p
    // chain and rejoins before k_agg. Host-side setup runs only during the
    // capture call (graph replays execute no host code). No device alloc.
    cudaStream_t s2 = 0;
    cudaEvent_t evFork = 0, evJoin = 0;
    bool forked = (cudaStreamCreateWithFlags(&s2, cudaStreamNonBlocking) == cudaSuccess) &&
                  (cudaEventCreateWithFlags(&evFork, cudaEventDisableTiming) == cudaSuccess) &&
                  (cudaEventCreateWithFlags(&evJoin, cudaEventDisableTiming) == cudaSuccess);

    cudaStream_t sb = 0;  // CSR-chain stream (falls back to default if fork failed)
    if (forked) {
        cudaEventRecord(evFork, 0);
        cudaStreamWaitEvent(s2, evFork, 0);
        sb = s2;
    }

    // --- CSR chain (side stream) ---
    k_zero<<<(2 * (N_NODE + 1) + 255) / 256, 256, 0, sb>>>();
    k_count<<<1184, 256, 0, sb>>>(edge_src, edge_dst);
    k_scan<<<2, 1024, 0, sb>>>();
    k_scatter<<<1184, 256, 0, sb>>>(edge_src, edge_dst);
    if (forked) cudaEventRecord(evJoin, sb);

    // --- message chain (default stream) ---
    // 1. W = att @ basis
    k_W<<<(RATES * VOCAB * MS + 255) / 256, 256>>>(att, basis);
    // 2. M[r][k] = W[r] @ fc_w_k^T  (fp16 output)
    dim3 gM(VOCAB / 64, OUTU / 64, RATES * 3);
    k_M<<<gM, 256>>>(fc_w);
    // 3. node messages p (both sides, both ratings) -> fp16
    int warps = 2 * RATES * N_NODE;
    k_p<<<(warps + 7) / 8, 256>>>(drug_feat, dis_feat, cj_drug, cj_dis);

    // --- join, then aggregate ---
    if (forked) cudaStreamWaitEvent(0, evJoin, 0);
    int ablocks = (N_NODE + 7) / 8;
    k_agg<<<ablocks, 256>>>(0, ci_drug, ci_dis, fc_b, out);
    k_agg<<<ablocks, 256>>>(1, ci_drug, ci_dis, fc_b, out);
    // Intentionally do not destroy s2/events: kernel_launch runs only a few
    // times (correctness + capture); destroying capture-referenced handles
    // mid-capture is riskier than a tiny host-side leak.
}